// round 8
// baseline (speedup 1.0000x reference)
#include <cuda_runtime.h>
#include <math.h>

// ---------------- problem constants ----------------
#define NB   2        // batch
#define H1   128      // conv1/conv2 spatial
#define W1   128
#define HP   63       // pooled spatial
#define NQ   8        // 4 crops * batch 2
#define HO   48       // conv5 output spatial
#define PX5  2304     // 48*48

// ---------------- intermediate buffers (device globals; no allocation) ----------------
__device__ float g_a[NB*64*H1*W1];     // conv1 out            (8 MB)
__device__ float g_b[NB*64*H1*W1];     // conv2+LRN out        (8 MB)
__device__ float g_p[NQ*64*HP*HP];     // crops+maxpool out    (8.1 MB)
__device__ float g_c[NQ*64*HP*HP];     // conv3 out
__device__ float g_d[NQ*64*HP*HP];     // conv4+LRN out
__device__ float g_e[NQ*1024*HO*HO];   // conv5 out            (75.5 MB)
__device__ float g_f[NQ*1024*HO*HO];   // conv6 out            (75.5 MB)

// =====================================================================
// Generic 64-output-channel direct conv, SAME padding, 16x16 spatial tile.
// Thread microtile: 8 co x 8 px (fixed col, rows rbase, rbase+2, ...).
// Warp = one co-group -> weight LDS are uniform (broadcast).
// Patch rows padded to stride 48 (48 mod 32 == 16 -> conflict-free).
// Optional fused LRN (size=2, alpha=2e-5, beta=0.75, k=1).
// =====================================================================
template<int K, int CIN, int CCH, bool DO_LRN>
__global__ __launch_bounds__(256) void conv_tile(
    const float* __restrict__ in, const float* __restrict__ w,
    const float* __restrict__ bias, float* __restrict__ out,
    int H, int W)
{
    constexpr int KK    = K * K;
    constexpr int PAD   = K / 2;
    constexpr int PH    = 16 + K - 1;         // patch logical extent
    constexpr int PATCH = CCH * PH * 48;      // padded-stride patch
    constexpr int WELE  = 64 * CCH * KK;
    __shared__ float sm[PATCH + WELE];
    float* patch = sm;
    float* wsm   = sm + PATCH;

    const int tid   = threadIdx.x;
    const int cog   = tid >> 5;       // 0..7 (8 co per thread)
    const int pxt   = tid & 31;
    const int col   = pxt & 15;
    const int rbase = pxt >> 4;       // rows rbase + 2*i
    const int x0 = blockIdx.x * 16;
    const int y0 = blockIdx.y * 16;
    const int n  = blockIdx.z;

    float acc[8][8];
    #pragma unroll
    for (int c = 0; c < 8; c++)
        #pragma unroll
        for (int i = 0; i < 8; i++) acc[c][i] = 0.f;

    for (int cb = 0; cb < CIN; cb += CCH) {
        __syncthreads();
        // --- load input patch (zero-padded) ---
        for (int idx = tid; idx < CCH * PH * PH; idx += 256) {
            int ci = idx / (PH * PH);
            int rr = (idx / PH) % PH;
            int cc = idx % PH;
            int gy = y0 - PAD + rr;
            int gx = x0 - PAD + cc;
            float v = 0.f;
            if (gy >= 0 && gy < H && gx >= 0 && gx < W)
                v = in[((n * CIN + cb + ci) * H + gy) * W + gx];
            patch[(ci * PH + rr) * 48 + cc] = v;
        }
        // --- load weight chunk: wsm[co][ci][tap] ---
        for (int idx = tid; idx < WELE; idx += 256) {
            int co  = idx / (CCH * KK);
            int rem = idx % (CCH * KK);
            wsm[idx] = w[(co * CIN + cb) * KK + rem];
        }
        __syncthreads();

        #pragma unroll 1
        for (int ci = 0; ci < CCH; ci++) {
            const float* prow = &patch[ci * PH * 48];
            const float* wrow = &wsm[(cog * 8) * CCH * KK + ci * KK];
            #pragma unroll 1
            for (int ky = 0; ky < K; ky++) {
                #pragma unroll
                for (int kx = 0; kx < K; kx++) {
                    float v[8];
                    #pragma unroll
                    for (int i = 0; i < 8; i++)
                        v[i] = prow[(rbase + 2 * i + ky) * 48 + col + kx];
                    #pragma unroll
                    for (int c = 0; c < 8; c++) {
                        float wv = wrow[c * CCH * KK + ky * K + kx];
                        #pragma unroll
                        for (int i = 0; i < 8; i++)
                            acc[c][i] = fmaf(wv, v[i], acc[c][i]);
                    }
                }
            }
        }
    }

    // --- epilogue: bias + relu (+ LRN) ---
    #pragma unroll
    for (int c = 0; c < 8; c++) {
        float bb = bias[cog * 8 + c];
        #pragma unroll
        for (int i = 0; i < 8; i++)
            acc[c][i] = fmaxf(acc[c][i] + bb, 0.f);
    }

    if (DO_LRN) {
        __syncthreads();                 // everyone done reading patch
        float* edge = sm;                // reuse smem: [8 cog][32 pxt][8 i]
        #pragma unroll
        for (int i = 0; i < 8; i++)
            edge[(cog * 32 + pxt) * 8 + i] = acc[7][i];   // raw last channel of group
        __syncthreads();
        float prev[8];
        #pragma unroll
        for (int i = 0; i < 8; i++)
            prev[i] = (cog > 0) ? edge[((cog - 1) * 32 + pxt) * 8 + i] : 0.f;
        // descending c so acc[c-1] is still pre-LRN
        #pragma unroll
        for (int c = 7; c >= 0; c--) {
            #pragma unroll
            for (int i = 0; i < 8; i++) {
                float cur = acc[c][i];
                float pv  = (c > 0) ? acc[c - 1][i] : prev[i];
                float dnm = 1.f + 1e-5f * (pv * pv + cur * cur); // alpha*0.5 = 1e-5
                acc[c][i] = cur * powf(dnm, -0.75f);
            }
        }
    }

    // --- store ---
    #pragma unroll
    for (int c = 0; c < 8; c++) {
        int co = cog * 8 + c;
        #pragma unroll
        for (int i = 0; i < 8; i++) {
            int y = y0 + rbase + 2 * i;
            int x = x0 + col;
            if (y < H && x < W)
                out[((n * 64 + co) * H + y) * W + x] = acc[c][i];
        }
    }
}

// =====================================================================
// crops (4 shifted views) + 2x2/2 maxpool:  (2,64,128,128) -> (8,64,63,63)
// =====================================================================
__global__ void pool_kernel(const float* __restrict__ in, float* __restrict__ out)
{
    int id = blockIdx.x * 256 + threadIdx.x;
    if (id >= NQ * 64 * HP * HP) return;
    int j = id % HP;
    int i = (id / HP) % HP;
    int c = (id / (HP * HP)) % 64;
    int q = id / (64 * HP * HP);
    int n = q & 1;
    int crop = q >> 1;
    int dy = crop & 1;          // crop1 = h[1:, :-1]
    int dx = crop >> 1;         // crop2 = h[:-1, 1:]
    const float* base = in + ((size_t)(n * 64 + c) * H1) * W1;
    int y = dy + 2 * i, x = dx + 2 * j;
    float m = fmaxf(fmaxf(base[y * W1 + x],       base[y * W1 + x + 1]),
                    fmaxf(base[(y + 1) * W1 + x], base[(y + 1) * W1 + x + 1]));
    out[id] = m;
}

// =====================================================================
// conv5: 16x16 VALID, 64 -> 1024.  (8,64,63,63) -> (8,1024,48,48)
// Block: 64 co x 16x16 px tile; loop cin, weight tap-chunks of 64.
// =====================================================================
__global__ __launch_bounds__(256) void conv5_kernel(
    const float* __restrict__ in, const float* __restrict__ w,
    const float* __restrict__ bias, float* __restrict__ out)
{
    __shared__ float patch[31 * 48];
    __shared__ float wsm[64 * 64];

    const int tid   = threadIdx.x;
    const int cog   = tid >> 5;
    const int pxt   = tid & 31;
    const int col   = pxt & 15;
    const int rbase = pxt >> 4;
    const int bx = blockIdx.x, by = blockIdx.y;
    const int n   = blockIdx.z >> 4;
    const int cot = blockIdx.z & 15;

    float acc[8][8];
    #pragma unroll
    for (int c = 0; c < 8; c++)
        #pragma unroll
        for (int i = 0; i < 8; i++) acc[c][i] = 0.f;

    for (int ci = 0; ci < 64; ci++) {
        __syncthreads();
        // patch 31x31 (always in-bounds for VALID conv)
        for (int idx = tid; idx < 31 * 31; idx += 256) {
            int r = idx / 31, c2 = idx % 31;
            patch[r * 48 + c2] =
                in[((n * 64 + ci) * HP + by * 16 + r) * HP + bx * 16 + c2];
        }
        for (int tb = 0; tb < 256; tb += 64) {
            __syncthreads();
            for (int idx = tid; idx < 4096; idx += 256) {
                int coL = idx >> 6, t = idx & 63;
                wsm[idx] = w[((cot * 64 + coL) * 64 + ci) * 256 + tb + t];
            }
            __syncthreads();
            #pragma unroll 4
            for (int t = 0; t < 64; t++) {
                int tap = tb + t;
                int ky = tap >> 4, kx = tap & 15;
                float v[8];
                #pragma unroll
                for (int i = 0; i < 8; i++)
                    v[i] = patch[(rbase + 2 * i + ky) * 48 + col + kx];
                #pragma unroll
                for (int c = 0; c < 8; c++) {
                    float wv = wsm[(cog * 8 + c) * 64 + t];
                    #pragma unroll
                    for (int i = 0; i < 8; i++)
                        acc[c][i] = fmaf(wv, v[i], acc[c][i]);
                }
            }
        }
    }

    #pragma unroll
    for (int c = 0; c < 8; c++) {
        int co = cot * 64 + cog * 8 + c;
        float bb = bias[co];
        #pragma unroll
        for (int i = 0; i < 8; i++) {
            int y = by * 16 + rbase + 2 * i;
            int x = bx * 16 + col;
            out[((n * 1024 + co) * HO + y) * HO + x] = fmaxf(acc[c][i] + bb, 0.f);
        }
    }
}

// =====================================================================
// conv6: 1x1, 1024 -> 1024 == GEMM. Block: 64 co x 256 px, K-chunk 16.
// =====================================================================
__global__ __launch_bounds__(256) void conv6_kernel(
    const float* __restrict__ in, const float* __restrict__ w,
    const float* __restrict__ bias, float* __restrict__ out)
{
    __shared__ float Wsm[64 * 16];    // [co][kk]
    __shared__ float Bsm[16 * 256];   // [kk][px]

    const int tid = threadIdx.x;
    const int cog = tid >> 5;
    const int pxt = tid & 31;
    const int bx = blockIdx.x;        // px tile 0..8
    const int by = blockIdx.y;        // co tile 0..15
    const int q  = blockIdx.z;        // 0..7

    float acc[8][8];
    #pragma unroll
    for (int c = 0; c < 8; c++)
        #pragma unroll
        for (int i = 0; i < 8; i++) acc[c][i] = 0.f;

    for (int kb = 0; kb < 1024; kb += 16) {
        __syncthreads();
        for (int idx = tid; idx < 1024; idx += 256) {
            int co = idx >> 4, kk = idx & 15;
            Wsm[idx] = w[(by * 64 + co) * 1024 + kb + kk];
        }
        for (int idx = tid; idx < 4096; idx += 256) {
            int kk = idx >> 8, j = idx & 255;
            Bsm[idx] = in[(q * 1024 + kb + kk) * PX5 + bx * 256 + j];
        }
        __syncthreads();
        #pragma unroll 4
        for (int kk = 0; kk < 16; kk++) {
            float v[8];
            #pragma unroll
            for (int i = 0; i < 8; i++)
                v[i] = Bsm[kk * 256 + pxt + 32 * i];
            #pragma unroll
            for (int c = 0; c < 8; c++) {
                float wv = Wsm[(cog * 8 + c) * 16 + kk];
                #pragma unroll
                for (int i = 0; i < 8; i++)
                    acc[c][i] = fmaf(wv, v[i], acc[c][i]);
            }
        }
    }

    #pragma unroll
    for (int c = 0; c < 8; c++) {
        int co = by * 64 + cog * 8 + c;
        float bb = bias[co];
        #pragma unroll
        for (int i = 0; i < 8; i++) {
            int px = bx * 256 + pxt + 32 * i;
            out[(q * 1024 + co) * PX5 + px] = fmaxf(acc[c][i] + bb, 0.f);
        }
    }
}

// =====================================================================
// conv7 (1x1, 1024 -> 1) + sigmoid + interweave -> d_out (2,1,96,96)
// out[n, 2h+s, 2w+t] = y[n + 2s + 4t, h, w]
// =====================================================================
__global__ void conv7_kernel(const float* __restrict__ in,
                             const float* __restrict__ w7,
                             const float* __restrict__ b7,
                             float* __restrict__ out)
{
    int id = blockIdx.x * 256 + threadIdx.x;
    if (id >= NQ * PX5) return;
    int hw = id % PX5;
    int q  = id / PX5;
    float acc = b7[0];
    const float* p = in + (size_t)q * 1024 * PX5 + hw;
    #pragma unroll 4
    for (int ci = 0; ci < 1024; ci++)
        acc = fmaf(p[ci * PX5], w7[ci], acc);
    float s = 1.f / (1.f + expf(-acc));
    int h = hw / HO, wv = hw % HO;
    int n = q & 1, ss = (q >> 1) & 1, t = q >> 2;
    out[n * 96 * 96 + (2 * h + ss) * 96 + (2 * wv + t)] = s;
}

// =====================================================================
// launch
// =====================================================================
extern "C" void kernel_launch(void* const* d_in, const int* in_sizes, int n_in,
                              void* d_out, int out_size)
{
    const float* x  = (const float*)d_in[0];
    const float* w1 = (const float*)d_in[1];  const float* b1 = (const float*)d_in[2];
    const float* w2 = (const float*)d_in[3];  const float* b2 = (const float*)d_in[4];
    const float* w3 = (const float*)d_in[5];  const float* b3 = (const float*)d_in[6];
    const float* w4 = (const float*)d_in[7];  const float* b4 = (const float*)d_in[8];
    const float* w5 = (const float*)d_in[9];  const float* b5 = (const float*)d_in[10];
    const float* w6 = (const float*)d_in[11]; const float* b6 = (const float*)d_in[12];
    const float* w7 = (const float*)d_in[13]; const float* b7 = (const float*)d_in[14];

    void *pa, *pb, *pp, *pc, *pd, *pe, *pf;
    cudaGetSymbolAddress(&pa, g_a);
    cudaGetSymbolAddress(&pb, g_b);
    cudaGetSymbolAddress(&pp, g_p);
    cudaGetSymbolAddress(&pc, g_c);
    cudaGetSymbolAddress(&pd, g_d);
    cudaGetSymbolAddress(&pe, g_e);
    cudaGetSymbolAddress(&pf, g_f);

    // conv1: 7x7 SAME, 1->64, relu
    conv_tile<7, 1, 1, false><<<dim3(8, 8, NB), 256>>>(x, w1, b1, (float*)pa, H1, W1);
    // conv2: 5x5 SAME, 64->64, relu + LRN
    conv_tile<5, 64, 4, true><<<dim3(8, 8, NB), 256>>>((float*)pa, w2, b2, (float*)pb, H1, W1);
    // crops + maxpool
    pool_kernel<<<(NQ * 64 * HP * HP + 255) / 256, 256>>>((float*)pb, (float*)pp);
    // conv3: 3x3 SAME, relu
    conv_tile<3, 64, 8, false><<<dim3(4, 4, NQ), 256>>>((float*)pp, w3, b3, (float*)pc, HP, HP);
    // conv4: 3x3 SAME, relu + LRN
    conv_tile<3, 64, 8, true><<<dim3(4, 4, NQ), 256>>>((float*)pc, w4, b4, (float*)pd, HP, HP);
    // conv5: 16x16 VALID, 64->1024, relu
    conv5_kernel<<<dim3(3, 3, NQ * 16), 256>>>((float*)pd, w5, b5, (float*)pe);
    // conv6: 1x1, 1024->1024, relu
    conv6_kernel<<<dim3(9, 16, NQ), 256>>>((float*)pe, w6, b6, (float*)pf);
    // conv7 + sigmoid + interweave
    conv7_kernel<<<(NQ * PX5 + 255) / 256, 256>>>((float*)pf, w7, b7, (float*)d_out);
}